// round 10
// baseline (speedup 1.0000x reference)
#include <cuda_runtime.h>
#include <cstdint>

// Problem constants (fixed by the dataset)
#define BVAL   2048
#define TVAL   2048
#define HVAL   64
#define BTILE  5                    // max batches per CTA
#define THREADS 128                 // 4 warps per CTA
#define NSM    148
#define GRID   (3 * NSM)            // 444 CTAs -> 3 per SM (reg-capped)
#define NHEAVY 272                  // CTAs carrying 5 batches (rest carry 4)

#define TANH_C 2.885390082f         // 2*log2(e); folded into weights/bias

// ---------- packed f32x2 helpers (Blackwell) ----------
__device__ __forceinline__ unsigned long long ffma2(unsigned long long a,
                                                    unsigned long long b,
                                                    unsigned long long c) {
    unsigned long long d;
    asm("fma.rn.f32x2 %0, %1, %2, %3;" : "=l"(d) : "l"(a), "l"(b), "l"(c));
    return d;
}
__device__ __forceinline__ unsigned long long fadd2(unsigned long long a,
                                                    unsigned long long b) {
    unsigned long long d;
    asm("add.rn.f32x2 %0, %1, %2;" : "=l"(d) : "l"(a), "l"(b));
    return d;
}
__device__ __forceinline__ float lo32(unsigned long long v) {
    return __uint_as_float((unsigned)v);
}
__device__ __forceinline__ float hi32(unsigned long long v) {
    return __uint_as_float((unsigned)(v >> 32));
}
__device__ __forceinline__ unsigned long long pack2(float lo, float hi) {
    return (unsigned long long)__float_as_uint(lo) |
           ((unsigned long long)__float_as_uint(hi) << 32);
}

// Compiler-only ordering fence (no instruction). In-warp smem program order
// makes STS->LDS visible without WARPSYNC (warp privately owns its batches).
__device__ __forceinline__ void cfence() { asm volatile("" ::: "memory"); }

// tanh from PRE-SCALED input z = 2*log2(e)*s: tanh = 1 - 2/(ex2(z)+1).
__device__ __forceinline__ float tanh_scaled(float z) {
    float p; asm("ex2.approx.f32 %0, %1;" : "=f"(p) : "f"(z));
    float r; asm("rcp.approx.f32 %0, %1;" : "=f"(r) : "f"(p + 1.0f));
    return fmaf(-2.0f, r, 1.0f);
}

// Full time loop for a warp owning NB batches. Warp-private, sync-free.
// Lane owns contiguous rows j0=2*lane, j1=2*lane+1 (one STS.64 per batch-step).
// NB==2 uses 1 accumulator chain per (row,batch) to save registers (4
// independent chains across rows*batches keep the fma pipe fed); NB==1 uses 2.
template<int NB>
__device__ __forceinline__ void run_loop(
    const float* __restrict__ x, const float* __restrict__ W_ih,
    const float* __restrict__ W_hh, const float* __restrict__ b_ih,
    const float* __restrict__ b_hh, const float* __restrict__ W_fc,
    const float* __restrict__ b_fc, float* __restrict__ out,
    float (&hbuf)[BTILE][HVAL], int lane, int lslot, int gbatch)
{
    constexpr int CH = (NB == 2) ? 1 : 2;
    const int j0 = 2 * lane;

    // W_hh rows j0, j0+1: k-packed u64, PRE-SCALED by TANH_C (128 regs)
    unsigned long long wA[HVAL / 2], wB[HVAL / 2];
    {
        const float2* ra = reinterpret_cast<const float2*>(W_hh + j0 * HVAL);
        const float2* rb = reinterpret_cast<const float2*>(W_hh + (j0 + 1) * HVAL);
        #pragma unroll
        for (int k = 0; k < HVAL / 2; k++) {
            float2 a = ra[k], b = rb[k];
            wA[k] = pack2(a.x * TANH_C, a.y * TANH_C);
            wB[k] = pack2(b.x * TANH_C, b.y * TANH_C);
        }
    }
    const unsigned long long wihA =
        pack2(W_ih[2 * j0] * TANH_C, W_ih[2 * j0 + 1] * TANH_C);
    const unsigned long long wihB =
        pack2(W_ih[2 * j0 + 2] * TANH_C, W_ih[2 * j0 + 3] * TANH_C);
    const unsigned long long biasA = pack2((b_ih[j0] + b_hh[j0]) * TANH_C, 0.0f);
    const unsigned long long biasB =
        pack2((b_ih[j0 + 1] + b_hh[j0 + 1]) * TANH_C, 0.0f);

    #pragma unroll
    for (int b = 0; b < NB; b++)
        *reinterpret_cast<unsigned long long*>(&hbuf[lslot + b][j0]) = 0ull;
    cfence();

    // x streams: one float4 = two timesteps per batch (prefetch 2 steps ahead)
    const float4* xq[NB];
    float4 cur[NB];
    #pragma unroll
    for (int b = 0; b < NB; b++) {
        xq[b]  = reinterpret_cast<const float4*>(x + (size_t)(gbatch + b) * TVAL * 2);
        cur[b] = xq[b][0];
    }

    // one step, in place: read hbuf, then overwrite own rows (program order)
    auto do_step = [&](const float* xa, const float* xb) {
        unsigned long long accA[NB][CH], accB[NB][CH];
        #pragma unroll
        for (int b = 0; b < NB; b++) {
            unsigned long long xv = pack2(xa[b], xb[b]);
            accA[b][0] = ffma2(xv, wihA, biasA);
            accB[b][0] = ffma2(xv, wihB, biasB);
            #pragma unroll
            for (int c = 1; c < CH; c++) { accA[b][c] = 0ull; accB[b][c] = 0ull; }
        }
        const ulonglong2* hp[NB];
        #pragma unroll
        for (int b = 0; b < NB; b++)
            hp[b] = reinterpret_cast<const ulonglong2*>(&hbuf[lslot + b][0]);
        #pragma unroll
        for (int kk = 0; kk < HVAL / 4; kk++) {
            #pragma unroll
            for (int b = 0; b < NB; b++) {
                ulonglong2 hv = hp[b][kk];     // LDS.128, warp-broadcast
                accA[b][0]      = ffma2(hv.x, wA[2 * kk],     accA[b][0]);
                accA[b][CH - 1] = ffma2(hv.y, wA[2 * kk + 1], accA[b][CH - 1]);
                accB[b][0]      = ffma2(hv.x, wB[2 * kk],     accB[b][0]);
                accB[b][CH - 1] = ffma2(hv.y, wB[2 * kk + 1], accB[b][CH - 1]);
            }
        }
        cfence();   // LDS above stay above the STS below
        #pragma unroll
        for (int b = 0; b < NB; b++) {
            unsigned long long sA =
                (CH == 2) ? fadd2(accA[b][0], accA[b][CH - 1]) : accA[b][0];
            unsigned long long sB =
                (CH == 2) ? fadd2(accB[b][0], accB[b][CH - 1]) : accB[b][0];
            float tA = tanh_scaled(lo32(sA) + hi32(sA));
            float tB = tanh_scaled(lo32(sB) + hi32(sB));
            *reinterpret_cast<unsigned long long*>(&hbuf[lslot + b][j0]) =
                pack2(tA, tB);                 // STS.64, rows contiguous
        }
        cfence();
    };

    float xa[NB], xb[NB];
    #pragma unroll 1
    for (int t = 0; t < TVAL; t += 2) {
        int tn = (t + 2 < TVAL) ? (t / 2 + 1) : (TVAL / 2 - 1);
        float4 nxt[NB];
        #pragma unroll
        for (int b = 0; b < NB; b++) nxt[b] = xq[b][tn];

        #pragma unroll
        for (int b = 0; b < NB; b++) { xa[b] = cur[b].x; xb[b] = cur[b].y; }
        do_step(xa, xb);
        #pragma unroll
        for (int b = 0; b < NB; b++) { xa[b] = cur[b].z; xb[b] = cur[b].w; }
        do_step(xa, xb);

        #pragma unroll
        for (int b = 0; b < NB; b++) cur[b] = nxt[b];
    }

    __syncwarp();   // once, before cross-lane read-back

    // Final FC on h_T. O=2 per batch; lanes 0..2*NB-1 cover (batch, output).
    if (lane < 2 * NB) {
        const int which = lane >> 1;
        const int oj    = lane & 1;
        const float* hv  = &hbuf[lslot + which][0];
        const float* wfc = W_fc + oj * HVAL;
        float acc = b_fc[oj];
        #pragma unroll
        for (int k = 0; k < HVAL; k++)
            acc = fmaf(hv[k], wfc[k], acc);
        out[(gbatch + which) * 2 + oj] = acc;
    }
}

__global__ void __launch_bounds__(THREADS, 3)
rnn_kernel(const float* __restrict__ x,     // [B,T,2]
           const float* __restrict__ W_ih,  // [64,2]
           const float* __restrict__ W_hh,  // [64,64]
           const float* __restrict__ b_ih,  // [64]
           const float* __restrict__ b_hh,  // [64]
           const float* __restrict__ W_fc,  // [2,64]
           const float* __restrict__ b_fc,  // [2]
           float* __restrict__ out)         // [B,2]
{
    __shared__ __align__(16) float hbuf[BTILE][HVAL];

    const int bid  = blockIdx.x;
    const int w    = threadIdx.x >> 5;
    const int lane = threadIdx.x & 31;

    // Heavy CTAs (bid < 272) carry 5 batches: one warp takes 2. The heavy
    // warp rotates with the wave index (148 % 4 == 0, so co-resident CTAs
    // bid, bid+148, bid+296 would otherwise load the same SMSP).
    int nb, lslot, gbatch;
    if (bid < NHEAVY) {
        const int hw = ((bid & 3) + (bid / NSM)) & 3;
        nb    = (w == hw) ? 2 : 1;
        lslot = w + (w > hw ? 1 : 0);
        gbatch = bid * 5 + lslot;
    } else {
        nb     = 1;
        lslot  = w;
        gbatch = NHEAVY * 5 + (bid - NHEAVY) * 4 + w;
    }

    if (nb == 2)
        run_loop<2>(x, W_ih, W_hh, b_ih, b_hh, W_fc, b_fc, out,
                    hbuf, lane, lslot, gbatch);
    else
        run_loop<1>(x, W_ih, W_hh, b_ih, b_hh, W_fc, b_fc, out,
                    hbuf, lane, lslot, gbatch);
}

extern "C" void kernel_launch(void* const* d_in, const int* in_sizes, int n_in,
                              void* d_out, int out_size) {
    const float* x    = (const float*)d_in[0];
    const float* W_ih = (const float*)d_in[1];
    const float* W_hh = (const float*)d_in[2];
    const float* b_ih = (const float*)d_in[3];
    const float* b_hh = (const float*)d_in[4];
    const float* W_fc = (const float*)d_in[5];
    const float* b_fc = (const float*)d_in[6];
    rnn_kernel<<<GRID, THREADS>>>(x, W_ih, W_hh, b_ih, b_hh,
                                  W_fc, b_fc, (float*)d_out);
}

// round 11
// speedup vs baseline: 1.0694x; 1.0694x over previous
#include <cuda_runtime.h>
#include <cstdint>

// Problem constants (fixed by the dataset)
#define BVAL   2048
#define TVAL   2048
#define HVAL   64
#define NBW    2                    // batches per warp
#define WARPS  4                    // warps per CTA
#define BTILE  (NBW * WARPS)        // 8 batches per CTA
#define THREADS (WARPS * 32)        // 128 threads
#define GRID   (BVAL / BTILE)       // 256 CTAs, 2/SM resident

#define TANH_C 2.885390082f         // 2*log2(e); folded into weights/bias

// ---------- packed f32x2 helpers (Blackwell) ----------
__device__ __forceinline__ unsigned long long ffma2(unsigned long long a,
                                                    unsigned long long b,
                                                    unsigned long long c) {
    unsigned long long d;
    asm("fma.rn.f32x2 %0, %1, %2, %3;" : "=l"(d) : "l"(a), "l"(b), "l"(c));
    return d;
}
__device__ __forceinline__ unsigned long long fadd2(unsigned long long a,
                                                    unsigned long long b) {
    unsigned long long d;
    asm("add.rn.f32x2 %0, %1, %2;" : "=l"(d) : "l"(a), "l"(b));
    return d;
}
__device__ __forceinline__ float lo32(unsigned long long v) {
    return __uint_as_float((unsigned)v);
}
__device__ __forceinline__ float hi32(unsigned long long v) {
    return __uint_as_float((unsigned)(v >> 32));
}
__device__ __forceinline__ unsigned long long pack2(float lo, float hi) {
    return (unsigned long long)__float_as_uint(lo) |
           ((unsigned long long)__float_as_uint(hi) << 32);
}

// Compiler-only ordering fence. In-warp smem program order makes STS->LDS
// visible without WARPSYNC (each warp privately owns its batches).
__device__ __forceinline__ void cfence() { asm volatile("" ::: "memory"); }

// tanh from PRE-SCALED input z = 2*log2(e)*s: tanh = 1 - 2/(ex2(z)+1).
__device__ __forceinline__ float tanh_scaled(float z) {
    float p; asm("ex2.approx.f32 %0, %1;" : "=f"(p) : "f"(z));
    float r; asm("rcp.approx.f32 %0, %1;" : "=f"(r) : "f"(p + 1.0f));
    return fmaf(-2.0f, r, 1.0f);
}

__global__ void __launch_bounds__(THREADS, 2)
rnn_kernel(const float* __restrict__ x,     // [B,T,2]
           const float* __restrict__ W_ih,  // [64,2]
           const float* __restrict__ W_hh,  // [64,64]
           const float* __restrict__ b_ih,  // [64]
           const float* __restrict__ b_hh,  // [64]
           const float* __restrict__ W_fc,  // [2,64]
           const float* __restrict__ b_fc,  // [2]
           float* __restrict__ out)         // [B,2]
{
    // in-place hidden state, batch-major. Each warp owns 2 batches.
    __shared__ __align__(16) float hbuf[BTILE][HVAL];

    const int tid  = threadIdx.x;
    const int lane = tid & 31;
    const int w    = tid >> 5;
    const int j0   = 2 * lane;          // contiguous row pair -> STS.64
    const int bl0  = NBW * w;
    const int b0   = blockIdx.x * BTILE + bl0;

    // W_hh rows j0, j0+1: k-packed u64, pre-scaled by TANH_C (128 regs)
    unsigned long long wA[HVAL / 2], wB[HVAL / 2];
    {
        const float2* ra = reinterpret_cast<const float2*>(W_hh + j0 * HVAL);
        const float2* rb = reinterpret_cast<const float2*>(W_hh + (j0 + 1) * HVAL);
        #pragma unroll
        for (int k = 0; k < HVAL / 2; k++) {
            float2 a = ra[k], b = rb[k];
            wA[k] = pack2(a.x * TANH_C, a.y * TANH_C);
            wB[k] = pack2(b.x * TANH_C, b.y * TANH_C);
        }
    }
    // input-weight/bias scalars per owned row (pre-scaled)
    const float wA0 = W_ih[2 * j0] * TANH_C,     wA1 = W_ih[2 * j0 + 1] * TANH_C;
    const float wB0 = W_ih[2 * j0 + 2] * TANH_C, wB1 = W_ih[2 * j0 + 3] * TANH_C;
    const float bA  = (b_ih[j0] + b_hh[j0]) * TANH_C;
    const float bB  = (b_ih[j0 + 1] + b_hh[j0 + 1]) * TANH_C;

    // h0 = 0 for both batches
    *reinterpret_cast<unsigned long long*>(&hbuf[bl0 + 0][j0]) = 0ull;
    *reinterpret_cast<unsigned long long*>(&hbuf[bl0 + 1][j0]) = 0ull;
    cfence();

    const ulonglong2* hp0 =
        reinterpret_cast<const ulonglong2*>(&hbuf[bl0 + 0][0]);
    const ulonglong2* hp1 =
        reinterpret_cast<const ulonglong2*>(&hbuf[bl0 + 1][0]);

    // x streams: one float4 = two timesteps per batch
    const float4* xq0 = reinterpret_cast<const float4*>(x + (size_t)(b0 + 0) * TVAL * 2);
    const float4* xq1 = reinterpret_cast<const float4*>(x + (size_t)(b0 + 1) * TVAL * 2);
    float4 c0 = xq0[0];
    float4 c1 = xq1[0];

    // One batch-step: MAC (16 LDS.128, 64 FFMA2 in 4 chains) then TAIL
    // (hadd+tanh+STS.64). Called alternately for the two batches so each
    // batch's TAIL fills the other's LDS-latency window.
    auto batch_step = [&](const ulonglong2* hp, int slot, float x0, float x1) {
        // bases: row j0 -> chain a0, row j0+1 -> chain a2
        unsigned long long a0 = pack2(fmaf(x0, wA0, fmaf(x1, wA1, bA)), 0.0f);
        unsigned long long a2 = pack2(fmaf(x0, wB0, fmaf(x1, wB1, bB)), 0.0f);
        unsigned long long a1 = 0ull, a3 = 0ull;
        #pragma unroll
        for (int kk = 0; kk < HVAL / 4; kk++) {
            ulonglong2 hv = hp[kk];            // LDS.128, warp-broadcast
            a0 = ffma2(hv.x, wA[2 * kk],     a0);
            a1 = ffma2(hv.y, wA[2 * kk + 1], a1);
            a2 = ffma2(hv.x, wB[2 * kk],     a2);
            a3 = ffma2(hv.y, wB[2 * kk + 1], a3);
        }
        cfence();
        unsigned long long sA = fadd2(a0, a1);
        unsigned long long sB = fadd2(a2, a3);
        float tA = tanh_scaled(lo32(sA) + hi32(sA));
        float tB = tanh_scaled(lo32(sB) + hi32(sB));
        *reinterpret_cast<unsigned long long*>(&hbuf[bl0 + slot][j0]) =
            pack2(tA, tB);
        cfence();
    };

    #pragma unroll 1
    for (int t = 0; t < TVAL; t += 2) {
        int tn = (t + 2 < TVAL) ? (t / 2 + 1) : (TVAL / 2 - 1);
        float4 n0 = xq0[tn];
        float4 n1 = xq1[tn];
        batch_step(hp0, 0, c0.x, c0.y);    // step t,   batch 0
        batch_step(hp1, 1, c1.x, c1.y);    // step t,   batch 1
        batch_step(hp0, 0, c0.z, c0.w);    // step t+1, batch 0
        batch_step(hp1, 1, c1.z, c1.w);    // step t+1, batch 1
        c0 = n0;
        c1 = n1;
    }

    __syncwarp();   // once, before cross-lane read-back

    // Final FC on h_T. O=2 per batch; lanes 0..3 cover (batch, output) combos.
    if (lane < 2 * NBW) {
        const int which = lane >> 1;
        const int oj    = lane & 1;
        const float* hv  = &hbuf[bl0 + which][0];
        const float* wfc = W_fc + oj * HVAL;
        float acc = b_fc[oj];
        #pragma unroll
        for (int k = 0; k < HVAL; k++)
            acc = fmaf(hv[k], wfc[k], acc);
        out[(b0 + which) * 2 + oj] = acc;
    }
}

extern "C" void kernel_launch(void* const* d_in, const int* in_sizes, int n_in,
                              void* d_out, int out_size) {
    const float* x    = (const float*)d_in[0];
    const float* W_ih = (const float*)d_in[1];
    const float* W_hh = (const float*)d_in[2];
    const float* b_ih = (const float*)d_in[3];
    const float* b_hh = (const float*)d_in[4];
    const float* W_fc = (const float*)d_in[5];
    const float* b_fc = (const float*)d_in[6];
    rnn_kernel<<<GRID, THREADS>>>(x, W_ih, W_hh, b_ih, b_hh,
                                  W_fc, b_fc, (float*)d_out);
}

// round 12
// speedup vs baseline: 1.1931x; 1.1157x over previous
#include <cuda_runtime.h>
#include <cstdint>

// Problem constants (fixed by the dataset)
#define BVAL   2048
#define TVAL   2048
#define HVAL   64
#define NBW    2                    // batches per warp
#define WARPS  4                    // warps per CTA
#define BTILE  (NBW * WARPS)        // 8 batches per CTA
#define THREADS (WARPS * 32)        // 128 threads
#define GRID   (BVAL / BTILE)       // 256 CTAs, 2/SM resident

#define TANH_C 2.885390082f         // 2*log2(e); folded into weights/bias

// ---------- packed f32x2 helpers (Blackwell) ----------
__device__ __forceinline__ unsigned long long ffma2(unsigned long long a,
                                                    unsigned long long b,
                                                    unsigned long long c) {
    unsigned long long d;
    asm("fma.rn.f32x2 %0, %1, %2, %3;" : "=l"(d) : "l"(a), "l"(b), "l"(c));
    return d;
}
__device__ __forceinline__ unsigned long long fadd2(unsigned long long a,
                                                    unsigned long long b) {
    unsigned long long d;
    asm("add.rn.f32x2 %0, %1, %2;" : "=l"(d) : "l"(a), "l"(b));
    return d;
}
__device__ __forceinline__ float lo32(unsigned long long v) {
    return __uint_as_float((unsigned)v);
}
__device__ __forceinline__ float hi32(unsigned long long v) {
    return __uint_as_float((unsigned)(v >> 32));
}
__device__ __forceinline__ unsigned long long pack2(float lo, float hi) {
    return (unsigned long long)__float_as_uint(lo) |
           ((unsigned long long)__float_as_uint(hi) << 32);
}

// tanh from PRE-SCALED input z = 2*log2(e)*s: tanh = 1 - 2/(ex2(z)+1).
// No clamp needed: z->+inf gives ex2->inf, rcp->0, result 1 exactly;
// z->-inf gives ex2->0, rcp(1)=1, result -1 exactly. rel err ~1e-7/step.
__device__ __forceinline__ float tanh_scaled(float z) {
    float p; asm("ex2.approx.f32 %0, %1;" : "=f"(p) : "f"(z));
    float r; asm("rcp.approx.f32 %0, %1;" : "=f"(r) : "f"(p + 1.0f));
    return fmaf(-2.0f, r, 1.0f);
}

__global__ void __launch_bounds__(THREADS, 2)
rnn_kernel(const float* __restrict__ x,     // [B,T,2]
           const float* __restrict__ W_ih,  // [64,2]
           const float* __restrict__ W_hh,  // [64,64]
           const float* __restrict__ b_ih,  // [64]
           const float* __restrict__ b_hh,  // [64]
           const float* __restrict__ W_fc,  // [2,64]
           const float* __restrict__ b_fc,  // [2]
           float* __restrict__ out)         // [B,2]
{
    // double-buffered hidden state, batch-major. Each warp owns 2 batches;
    // no cross-warp synchronization needed after this point.
    __shared__ __align__(16) float hbuf[2][BTILE][HVAL];

    const int tid  = threadIdx.x;
    const int lane = tid & 31;
    const int w    = tid >> 5;          // warp 0..3
    const int j0   = lane;              // first output row this thread owns
    const int j1   = lane + 32;         // second output row
    const int bl0  = NBW * w;           // first local batch of this warp
    const int b0   = blockIdx.x * BTILE + bl0;

    // W_hh rows j0 and j1, k-packed into 32 u64 registers each, PRE-SCALED
    // by TANH_C (128 regs total, shared across both batches)
    unsigned long long wA[HVAL / 2], wB[HVAL / 2];
    {
        const float2* ra = reinterpret_cast<const float2*>(W_hh + j0 * HVAL);
        const float2* rb = reinterpret_cast<const float2*>(W_hh + j1 * HVAL);
        #pragma unroll
        for (int k = 0; k < HVAL / 2; k++) {
            float2 a = ra[k], b = rb[k];
            wA[k] = pack2(a.x * TANH_C, a.y * TANH_C);
            wB[k] = pack2(b.x * TANH_C, b.y * TANH_C);
        }
    }
    const float wihA0 = W_ih[2 * j0] * TANH_C, wihA1 = W_ih[2 * j0 + 1] * TANH_C;
    const float wihB0 = W_ih[2 * j1] * TANH_C, wihB1 = W_ih[2 * j1 + 1] * TANH_C;
    const float biasA = (b_ih[j0] + b_hh[j0]) * TANH_C;
    const float biasB = (b_ih[j1] + b_hh[j1]) * TANH_C;

    // h0 = 0 for both batches (each lane initializes its own 2 rows)
    hbuf[0][bl0 + 0][j0] = 0.0f;  hbuf[0][bl0 + 0][j1] = 0.0f;
    hbuf[0][bl0 + 1][j0] = 0.0f;  hbuf[0][bl0 + 1][j1] = 0.0f;
    __syncwarp();

    // ---- PHASE SKEW: odd warps burn ~half a step of fma-pipe time so the
    // two warps per SMSP run tail-phases in anti-phase (one warp's MACs
    // cover the other's tanh/STS tail). Dummy FFMA2 chain over the weight
    // regs, sunk behind a data-dependent never-true guard (compiler and
    // scheduler must keep it; it never stores in practice).
    if (w & 1) {
        unsigned long long d0 = wA[0], d1 = wA[1], d2 = wA[2], d3 = wA[3];
        #pragma unroll
        for (int k = 0; k < 8; k++) {
            d0 = ffma2(d0, wA[4 * (k & 7)],     d0);
            d1 = ffma2(d1, wA[4 * (k & 7) + 1], d1);
            d2 = ffma2(d2, wA[4 * (k & 7) + 2], d2);
            d3 = ffma2(d3, wA[4 * (k & 7) + 3], d3);
        }
        if (biasA > 1.0e37f)   // never true for this model's data
            hbuf[0][bl0][j0] = lo32(fadd2(fadd2(d0, d1), fadd2(d2, d3)));
    }

    // x streams: one float4 = two timesteps, per batch (warp-uniform address)
    const float4* xq0 = reinterpret_cast<const float4*>(x + (size_t)(b0 + 0) * TVAL * 2);
    const float4* xq1 = reinterpret_cast<const float4*>(x + (size_t)(b0 + 1) * TVAL * 2);
    float4 c0 = xq0[0];
    float4 c1 = xq1[0];

    // one RNN step for both batches: read hbuf[RB], write hbuf[WB].
    // Batches interleaved at instruction level (proven best in R6).
    #define RNN_STEP(RB, WB, XA0, XB0, XA1, XB1)                                 \
    {                                                                            \
        float baseA0 = fmaf((XA0), wihA0, fmaf((XB0), wihA1, biasA));            \
        float baseB0 = fmaf((XA0), wihB0, fmaf((XB0), wihB1, biasB));            \
        float baseA1 = fmaf((XA1), wihA0, fmaf((XB1), wihA1, biasA));            \
        float baseB1 = fmaf((XA1), wihB0, fmaf((XB1), wihB1, biasB));            \
        unsigned long long aA0 = pack2(baseA0, 0.0f), aA0b = 0ull;               \
        unsigned long long aB0 = pack2(baseB0, 0.0f), aB0b = 0ull;               \
        unsigned long long aA1 = pack2(baseA1, 0.0f), aA1b = 0ull;               \
        unsigned long long aB1 = pack2(baseB1, 0.0f), aB1b = 0ull;               \
        const ulonglong2* hp0 =                                                  \
            reinterpret_cast<const ulonglong2*>(&hbuf[(RB)][bl0 + 0][0]);        \
        const ulonglong2* hp1 =                                                  \
            reinterpret_cast<const ulonglong2*>(&hbuf[(RB)][bl0 + 1][0]);        \
        _Pragma("unroll")                                                        \
        for (int kk = 0; kk < HVAL / 4; kk++) {                                  \
            ulonglong2 hv0 = hp0[kk];          /* LDS.128, broadcast */          \
            ulonglong2 hv1 = hp1[kk];                                            \
            aA0  = ffma2(hv0.x, wA[2 * kk],     aA0);                            \
            aA0b = ffma2(hv0.y, wA[2 * kk + 1], aA0b);                           \
            aB0  = ffma2(hv0.x, wB[2 * kk],     aB0);                            \
            aB0b = ffma2(hv0.y, wB[2 * kk + 1], aB0b);                           \
            aA1  = ffma2(hv1.x, wA[2 * kk],     aA1);                            \
            aA1b = ffma2(hv1.y, wA[2 * kk + 1], aA1b);                           \
            aB1  = ffma2(hv1.x, wB[2 * kk],     aB1);                            \
            aB1b = ffma2(hv1.y, wB[2 * kk + 1], aB1b);                           \
        }                                                                        \
        unsigned long long sA0 = fadd2(aA0, aA0b);                               \
        unsigned long long sB0 = fadd2(aB0, aB0b);                               \
        unsigned long long sA1 = fadd2(aA1, aA1b);                               \
        unsigned long long sB1 = fadd2(aB1, aB1b);                               \
        hbuf[(WB)][bl0 + 0][j0] = tanh_scaled(lo32(sA0) + hi32(sA0));            \
        hbuf[(WB)][bl0 + 0][j1] = tanh_scaled(lo32(sB0) + hi32(sB0));            \
        hbuf[(WB)][bl0 + 1][j0] = tanh_scaled(lo32(sA1) + hi32(sA1));            \
        hbuf[(WB)][bl0 + 1][j1] = tanh_scaled(lo32(sB1) + hi32(sB1));            \
        __syncwarp();                                                            \
    }

    #pragma unroll 1
    for (int t = 0; t < TVAL; t += 2) {
        // prefetch next pair of timesteps (clamped on the last iteration)
        int tn = (t + 2 < TVAL) ? (t / 2 + 1) : (TVAL / 2 - 1);
        float4 n0 = xq0[tn];
        float4 n1 = xq1[tn];
        RNN_STEP(0, 1, c0.x, c0.y, c1.x, c1.y)
        RNN_STEP(1, 0, c0.z, c0.w, c1.z, c1.w)
        c0 = n0;
        c1 = n1;
    }
    #undef RNN_STEP

    // Final FC on h_T (in hbuf[0] after an even number of steps).
    // O=2, 2 batches per warp: lanes 0..3 cover (batch, output) combos.
    if (lane < 4) {
        const int which = lane >> 1;       // batch within warp pair
        const int oj    = lane & 1;        // output index 0/1
        const float* hv  = &hbuf[0][bl0 + which][0];
        const float* wfc = W_fc + oj * HVAL;
        float acc = b_fc[oj];
        #pragma unroll
        for (int k = 0; k < HVAL; k++)
            acc = fmaf(hv[k], wfc[k], acc);
        out[(b0 + which) * 2 + oj] = acc;
    }
}

extern "C" void kernel_launch(void* const* d_in, const int* in_sizes, int n_in,
                              void* d_out, int out_size) {
    const float* x    = (const float*)d_in[0];
    const float* W_ih = (const float*)d_in[1];
    const float* W_hh = (const float*)d_in[2];
    const float* b_ih = (const float*)d_in[3];
    const float* b_hh = (const float*)d_in[4];
    const float* W_fc = (const float*)d_in[5];
    const float* b_fc = (const float*)d_in[6];
    rnn_kernel<<<GRID, THREADS>>>(x, W_ih, W_hh, b_ih, b_hh,
                                  W_fc, b_fc, (float*)d_out);
}

// round 13
// speedup vs baseline: 1.2026x; 1.0080x over previous
#include <cuda_runtime.h>
#include <cstdint>

// Problem constants (fixed by the dataset)
#define BVAL   2048
#define TVAL   2048
#define HVAL   64
#define NBW    2                    // batches per warp
#define WARPS  4                    // warps per CTA
#define BTILE  (NBW * WARPS)        // 8 batches per CTA
#define THREADS (WARPS * 32)        // 128 threads
#define GRID   (BVAL / BTILE)       // 256 CTAs, 2/SM resident

#define TANH_C 2.885390082f         // 2*log2(e); folded into weights/bias

// ---------- packed f32x2 helpers (Blackwell) ----------
__device__ __forceinline__ unsigned long long ffma2(unsigned long long a,
                                                    unsigned long long b,
                                                    unsigned long long c) {
    unsigned long long d;
    asm("fma.rn.f32x2 %0, %1, %2, %3;" : "=l"(d) : "l"(a), "l"(b), "l"(c));
    return d;
}
__device__ __forceinline__ unsigned long long fadd2(unsigned long long a,
                                                    unsigned long long b) {
    unsigned long long d;
    asm("add.rn.f32x2 %0, %1, %2;" : "=l"(d) : "l"(a), "l"(b));
    return d;
}
__device__ __forceinline__ float lo32(unsigned long long v) {
    return __uint_as_float((unsigned)v);
}
__device__ __forceinline__ float hi32(unsigned long long v) {
    return __uint_as_float((unsigned)(v >> 32));
}
__device__ __forceinline__ unsigned long long pack2(float lo, float hi) {
    return (unsigned long long)__float_as_uint(lo) |
           ((unsigned long long)__float_as_uint(hi) << 32);
}

// tanh from PRE-SCALED input z = 2*log2(e)*s: tanh = 1 - 2/(ex2(z)+1).
// No clamp needed: z->+inf gives ex2->inf, rcp->0, result 1 exactly;
// z->-inf gives ex2->0, rcp(1)=1, result -1 exactly. rel err ~1e-7/step.
__device__ __forceinline__ float tanh_scaled(float z) {
    float p; asm("ex2.approx.f32 %0, %1;" : "=f"(p) : "f"(z));
    float r; asm("rcp.approx.f32 %0, %1;" : "=f"(r) : "f"(p + 1.0f));
    return fmaf(-2.0f, r, 1.0f);
}

__global__ void __launch_bounds__(THREADS, 2)
rnn_kernel(const float* __restrict__ x,     // [B,T,2]
           const float* __restrict__ W_ih,  // [64,2]
           const float* __restrict__ W_hh,  // [64,64]
           const float* __restrict__ b_ih,  // [64]
           const float* __restrict__ b_hh,  // [64]
           const float* __restrict__ W_fc,  // [2,64]
           const float* __restrict__ b_fc,  // [2]
           float* __restrict__ out)         // [B,2]
{
    // double-buffered hidden state, batch-major. Each warp owns 2 batches;
    // no cross-warp synchronization needed after this point.
    __shared__ __align__(16) float hbuf[2][BTILE][HVAL];

    const int tid  = threadIdx.x;
    const int lane = tid & 31;
    const int w    = tid >> 5;          // warp 0..3
    const int bid  = blockIdx.x;
    const int j0   = lane;              // first output row this thread owns
    const int j1   = lane + 32;         // second output row
    const int bl0  = NBW * w;           // first local batch of this warp
    const int b0   = bid * BTILE + bl0;

    // W_hh rows j0 and j1, k-packed into 32 u64 registers each, PRE-SCALED
    // by TANH_C (128 regs total, shared across both batches)
    unsigned long long wA[HVAL / 2], wB[HVAL / 2];
    {
        const float2* ra = reinterpret_cast<const float2*>(W_hh + j0 * HVAL);
        const float2* rb = reinterpret_cast<const float2*>(W_hh + j1 * HVAL);
        #pragma unroll
        for (int k = 0; k < HVAL / 2; k++) {
            float2 a = ra[k], b = rb[k];
            wA[k] = pack2(a.x * TANH_C, a.y * TANH_C);
            wB[k] = pack2(b.x * TANH_C, b.y * TANH_C);
        }
    }
    const float wihA0 = W_ih[2 * j0] * TANH_C, wihA1 = W_ih[2 * j0 + 1] * TANH_C;
    const float wihB0 = W_ih[2 * j1] * TANH_C, wihB1 = W_ih[2 * j1 + 1] * TANH_C;
    const float biasA = (b_ih[j0] + b_hh[j0]) * TANH_C;
    const float biasB = (b_ih[j1] + b_hh[j1]) * TANH_C;

    // h0 = 0 for both batches (each lane initializes its own 2 rows)
    hbuf[0][bl0 + 0][j0] = 0.0f;  hbuf[0][bl0 + 0][j1] = 0.0f;
    hbuf[0][bl0 + 1][j0] = 0.0f;  hbuf[0][bl0 + 1][j1] = 0.0f;
    __syncwarp();

    // ---- GRADED PHASE SKEW (R11 win, amplified). 4 phases from two bits:
    //   warp-parity bit  -> desyncs LDS bursts across SMSPs (shared L1)
    //   CTA-wave bit     -> desyncs the two co-resident warps per SMSP
    //                        (CTAs bid and bid+148 share an SM in a 2-wave
    //                         classic launch)
    // Each phase unit = dependent chain of 16 FFMA2 (~64 cyc).
    {
        const int phase = (w & 1) + ((bid >= 148) ? 2 : 0);
        if (phase) {
            unsigned long long d0 = wA[0];
            const int n = phase * 16;
            #pragma unroll 1
            for (int k = 0; k < n; k++)
                d0 = ffma2(d0, wA[k & 31], d0);   // serial: 4 cyc/link
            if (biasA > 1.0e37f)   // never true for this model's data
                hbuf[0][bl0][j0] = lo32(d0);
        }
    }

    // x streams: one float4 = two timesteps, per batch (warp-uniform address)
    const float4* xq0 = reinterpret_cast<const float4*>(x + (size_t)(b0 + 0) * TVAL * 2);
    const float4* xq1 = reinterpret_cast<const float4*>(x + (size_t)(b0 + 1) * TVAL * 2);
    float4 c0 = xq0[0];
    float4 c1 = xq1[0];

    // one RNN step for both batches: read hbuf[RB], write hbuf[WB].
    // Batches interleaved at instruction level (proven best in R6).
    #define RNN_STEP(RB, WB, XA0, XB0, XA1, XB1)                                 \
    {                                                                            \
        float baseA0 = fmaf((XA0), wihA0, fmaf((XB0), wihA1, biasA));            \
        float baseB0 = fmaf((XA0), wihB0, fmaf((XB0), wihB1, biasB));            \
        float baseA1 = fmaf((XA1), wihA0, fmaf((XB1), wihA1, biasA));            \
        float baseB1 = fmaf((XA1), wihB0, fmaf((XB1), wihB1, biasB));            \
        unsigned long long aA0 = pack2(baseA0, 0.0f), aA0b = 0ull;               \
        unsigned long long aB0 = pack2(baseB0, 0.0f), aB0b = 0ull;               \
        unsigned long long aA1 = pack2(baseA1, 0.0f), aA1b = 0ull;               \
        unsigned long long aB1 = pack2(baseB1, 0.0f), aB1b = 0ull;               \
        const ulonglong2* hp0 =                                                  \
            reinterpret_cast<const ulonglong2*>(&hbuf[(RB)][bl0 + 0][0]);        \
        const ulonglong2* hp1 =                                                  \
            reinterpret_cast<const ulonglong2*>(&hbuf[(RB)][bl0 + 1][0]);        \
        _Pragma("unroll")                                                        \
        for (int kk = 0; kk < HVAL / 4; kk++) {                                  \
            ulonglong2 hv0 = hp0[kk];          /* LDS.128, broadcast */          \
            ulonglong2 hv1 = hp1[kk];                                            \
            aA0  = ffma2(hv0.x, wA[2 * kk],     aA0);                            \
            aA0b = ffma2(hv0.y, wA[2 * kk + 1], aA0b);                           \
            aB0  = ffma2(hv0.x, wB[2 * kk],     aB0);                            \
            aB0b = ffma2(hv0.y, wB[2 * kk + 1], aB0b);                           \
            aA1  = ffma2(hv1.x, wA[2 * kk],     aA1);                            \
            aA1b = ffma2(hv1.y, wA[2 * kk + 1], aA1b);                           \
            aB1  = ffma2(hv1.x, wB[2 * kk],     aB1);                            \
            aB1b = ffma2(hv1.y, wB[2 * kk + 1], aB1b);                           \
        }                                                                        \
        unsigned long long sA0 = fadd2(aA0, aA0b);                               \
        unsigned long long sB0 = fadd2(aB0, aB0b);                               \
        unsigned long long sA1 = fadd2(aA1, aA1b);                               \
        unsigned long long sB1 = fadd2(aB1, aB1b);                               \
        hbuf[(WB)][bl0 + 0][j0] = tanh_scaled(lo32(sA0) + hi32(sA0));            \
        hbuf[(WB)][bl0 + 0][j1] = tanh_scaled(lo32(sB0) + hi32(sB0));            \
        hbuf[(WB)][bl0 + 1][j0] = tanh_scaled(lo32(sA1) + hi32(sA1));            \
        hbuf[(WB)][bl0 + 1][j1] = tanh_scaled(lo32(sB1) + hi32(sB1));            \
        __syncwarp();                                                            \
    }

    #pragma unroll 1
    for (int t = 0; t < TVAL; t += 2) {
        // prefetch next pair of timesteps (clamped on the last iteration)
        int tn = (t + 2 < TVAL) ? (t / 2 + 1) : (TVAL / 2 - 1);
        float4 n0 = xq0[tn];
        float4 n1 = xq1[tn];
        RNN_STEP(0, 1, c0.x, c0.y, c1.x, c1.y)
        RNN_STEP(1, 0, c0.z, c0.w, c1.z, c1.w)
        c0 = n0;
        c1 = n1;
    }
    #undef RNN_STEP

    // Final FC on h_T (in hbuf[0] after an even number of steps).
    // O=2, 2 batches per warp: lanes 0..3 cover (batch, output) combos.
    if (lane < 4) {
        const int which = lane >> 1;       // batch within warp pair
        const int oj    = lane & 1;        // output index 0/1
        const float* hv  = &hbuf[0][bl0 + which][0];
        const float* wfc = W_fc + oj * HVAL;
        float acc = b_fc[oj];
        #pragma unroll
        for (int k = 0; k < HVAL; k++)
            acc = fmaf(hv[k], wfc[k], acc);
        out[(b0 + which) * 2 + oj] = acc;
    }
}

extern "C" void kernel_launch(void* const* d_in, const int* in_sizes, int n_in,
                              void* d_out, int out_size) {
    const float* x    = (const float*)d_in[0];
    const float* W_ih = (const float*)d_in[1];
    const float* W_hh = (const float*)d_in[2];
    const float* b_ih = (const float*)d_in[3];
    const float* b_hh = (const float*)d_in[4];
    const float* W_fc = (const float*)d_in[5];
    const float* b_fc = (const float*)d_in[6];
    rnn_kernel<<<GRID, THREADS>>>(x, W_ih, W_hh, b_ih, b_hh,
                                  W_fc, b_fc, (float*)d_out);
}